// round 14
// baseline (speedup 1.0000x reference)
#include <cuda_runtime.h>
#include <cuda_bf16.h>
#include <cuda_fp16.h>
#include <cstdint>

#define DI __device__ __forceinline__

// ---------------- problem constants ----------------
namespace {
constexpr int BB = 4096;        // batch
constexpr int DD = 1024;        // feature dim
constexpr int KK = 3000;        // prototypes
constexpr int KP = 3072;        // padded K
constexpr int MT = 8192;        // stacked rows (z1 then z2)
constexpr float INV_EPS = 20.0f;   // 1/0.05
constexpr float INV_T   = 10.0f;   // 1/0.1
constexpr int NCTA = 296;       // persistent grid: 148 SMs x 2 (co-resident)
}

// ---------------- scratch (device globals; no runtime alloc) ----------------
__device__ __nv_bfloat16 g_Abf[(size_t)MT * DD];   // 16.8 MB
__device__ __nv_bfloat16 g_Wbf[(size_t)KP * DD];   // 6.3 MB (rows >= 3000 zero)
__device__ __half        g_S[(size_t)MT * KP];     // 50.3 MB fp16 scores
__device__ float  g_colE[2 * KP];
__device__ float  g_cA[2 * KP];     // col sums, sinkhorn iter 2
__device__ float  g_cB[2 * KP];     // col sums, sinkhorn iter 3
__device__ float  g_lse[MT];
__device__ float  g_u[MT];
__device__ unsigned g_bar;          // persistent-kernel barrier counter
__device__ double g_loss;

// ---------------- helpers ----------------
DI uint32_t smem_u32(const void* p) {
    uint32_t a;
    asm("{ .reg .u64 t; cvta.to.shared.u64 t, %1; cvt.u32.u64 %0, t; }" : "=r"(a) : "l"(p));
    return a;
}

DI void cp_async16(uint32_t saddr, const void* gptr) {
    asm volatile("cp.async.cg.shared.global [%0], [%1], 16;"
                 :: "r"(saddr), "l"(gptr) : "memory");
}
#define CP_COMMIT()  asm volatile("cp.async.commit_group;" ::: "memory")
#define CP_WAIT(n)   asm volatile("cp.async.wait_group %0;" :: "n"(n) : "memory")

DI void ldsm4(uint32_t& r0, uint32_t& r1, uint32_t& r2, uint32_t& r3, uint32_t a) {
    asm volatile("ldmatrix.sync.aligned.m8n8.x4.shared.b16 {%0,%1,%2,%3}, [%4];"
                 : "=r"(r0), "=r"(r1), "=r"(r2), "=r"(r3) : "r"(a));
}

DI void mma16816(float* d, const uint32_t* a, const uint32_t* b) {
    asm volatile(
        "mma.sync.aligned.m16n8k16.row.col.f32.bf16.bf16.f32 "
        "{%0,%1,%2,%3}, {%4,%5,%6,%7}, {%8,%9}, {%0,%1,%2,%3};"
        : "+f"(d[0]), "+f"(d[1]), "+f"(d[2]), "+f"(d[3])
        : "r"(a[0]), "r"(a[1]), "r"(a[2]), "r"(a[3]), "r"(b[0]), "r"(b[1]));
}

// conflict-free swizzle for 128B-wide rows: chunk ^= row&7
DI uint32_t sw_off(int row, int ch) {
    return (uint32_t)(row * 128 + ((ch ^ (row & 7)) * 16));
}

// ---------------- kernel 0: zero accumulators ----------------
__global__ void k_zero() {
    int idx = blockIdx.x * blockDim.x + threadIdx.x;   // 8192 threads
    if (idx < 2 * KP) { g_colE[idx] = 0.f; g_cA[idx] = 0.f; g_cB[idx] = 0.f; }
    if (idx < MT) g_lse[idx] = 0.f;
    if (idx == 0) { g_loss = 0.0; g_bar = 0u; }
}

// ---------------- kernel 1: convert z1|z2 -> bf16 A, W -> bf16 (merged) -----
__global__ void k_conv(const float* __restrict__ z1, const float* __restrict__ z2,
                       const float* __restrict__ W) {
    int v = blockIdx.x * blockDim.x + threadIdx.x;     // 0..2883583
    if (v < 2097152) {
        const float* src = (v < 1048576) ? (z1 + 4 * (size_t)v)
                                         : (z2 + 4 * (size_t)(v - 1048576));
        float4 f = *reinterpret_cast<const float4*>(src);
        __nv_bfloat162* dst = reinterpret_cast<__nv_bfloat162*>(&g_Abf[4 * (size_t)v]);
        dst[0] = __floats2bfloat162_rn(f.x, f.y);
        dst[1] = __floats2bfloat162_rn(f.z, f.w);
    } else {
        int w = v - 2097152;                           // 0..786431
        int row = w >> 8;
        __nv_bfloat162 lo, hi;
        if (row < KK) {
            float4 f = *reinterpret_cast<const float4*>(W + 4 * (size_t)w);
            lo = __floats2bfloat162_rn(f.x, f.y);
            hi = __floats2bfloat162_rn(f.z, f.w);
        } else {
            lo = __floats2bfloat162_rn(0.f, 0.f);
            hi = lo;
        }
        __nv_bfloat162* dst = reinterpret_cast<__nv_bfloat162*>(&g_Wbf[4 * (size_t)w]);
        dst[0] = lo;
        dst[1] = hi;
    }
}

// ---------------- kernel 2: mma.sync GEMM + fused pass-A epilogue ------------
// (proven config: 128x128 tile, Kc=64, 3-stage, 2 CTAs/SM — 141.8us)
static constexpr int NK = 16;
static constexpr int STAGES = 3;
static constexpr int STAGE_BYTES = 32768;

__global__ __launch_bounds__(256, 2) void k_gemm() {
    __shared__ __align__(1024) uint8_t sm[STAGES * STAGE_BYTES];

    const int tid = threadIdx.x;
    const int wid = tid >> 5;
    const int lid = tid & 31;
    const int warp_m = wid >> 2;       // 0..1
    const int warp_n = wid & 3;        // 0..3
    const int ntile = blockIdx.x;
    const int rtile = blockIdx.y;
    const int arow0 = rtile * 128;
    const int brow0 = ntile * 128;

    const uint32_t sbase = smem_u32(sm);

    float acc[4][4][4];
#pragma unroll
    for (int mi = 0; mi < 4; mi++)
#pragma unroll
        for (int ni = 0; ni < 4; ni++)
#pragma unroll
            for (int c = 0; c < 4; c++) acc[mi][ni][c] = 0.f;

    auto issue_loads = [&](int kc, int stage) {
        const uint32_t st = sbase + stage * STAGE_BYTES;
#pragma unroll
        for (int i = 0; i < 4; i++) {
            int idx = tid + i * 256;        // 0..1023
            int row = idx >> 3;             // 0..127
            int ch  = idx & 7;              // 16B chunk in 128B row
            int kb  = kc * 64 + ch * 8;     // element offset in k
            uint32_t so = sw_off(row, ch);
            cp_async16(st + so,         &g_Abf[(size_t)(arow0 + row) * DD + kb]);
            cp_async16(st + 16384 + so, &g_Wbf[(size_t)(brow0 + row) * DD + kb]);
        }
    };

#pragma unroll
    for (int s = 0; s < STAGES - 1; s++) {
        issue_loads(s, s);
        CP_COMMIT();
    }

    const int a_rowoff = lid & 15;
    const int a_chsel  = lid >> 4;
    const int b_noff   = ((lid >> 4) & 1) * 8 + (lid & 7);
    const int b_khalf  = (lid >> 3) & 1;

    int stage = 0;
#pragma unroll 1
    for (int kc = 0; kc < NK; kc++) {
        CP_WAIT(1);
        __syncthreads();
        if (kc + STAGES - 1 < NK) {
            int ns = stage + (STAGES - 1);
            if (ns >= STAGES) ns -= STAGES;
            issue_loads(kc + STAGES - 1, ns);
        }
        CP_COMMIT();

        const uint32_t Ab = sbase + stage * STAGE_BYTES;
        const uint32_t Bb = Ab + 16384;
        stage = (stage + 1 == STAGES) ? 0 : stage + 1;

#pragma unroll
        for (int ks = 0; ks < 4; ks++) {
            uint32_t a[4][4];
            const int chA = ks * 2 + a_chsel;
#pragma unroll
            for (int mi = 0; mi < 4; mi++) {
                int row = warp_m * 64 + mi * 16 + a_rowoff;
                ldsm4(a[mi][0], a[mi][1], a[mi][2], a[mi][3], Ab + sw_off(row, chA));
            }
            uint32_t b[4][2];
            const int chB = ks * 2 + b_khalf;
#pragma unroll
            for (int p = 0; p < 2; p++) {
                int row = warp_n * 32 + p * 16 + b_noff;
                uint32_t r0, r1, r2, r3;
                ldsm4(r0, r1, r2, r3, Bb + sw_off(row, chB));
                b[2 * p][0] = r0; b[2 * p][1] = r1;
                b[2 * p + 1][0] = r2; b[2 * p + 1][1] = r3;
            }
#pragma unroll
            for (int mi = 0; mi < 4; mi++)
#pragma unroll
                for (int ni = 0; ni < 4; ni++)
                    mma16816(acc[mi][ni], a[mi], b[ni]);
        }
    }
    __syncthreads();

    const int g = lid >> 2;
    const int t = lid & 3;
    const int m = (arow0 >= BB) ? 1 : 0;

    float* colAcc = reinterpret_cast<float*>(sm);
    if (tid < 128) colAcc[tid] = 0.f;
    __syncthreads();

    float colSum[4][2];
#pragma unroll
    for (int ni = 0; ni < 4; ni++) { colSum[ni][0] = 0.f; colSum[ni][1] = 0.f; }

#pragma unroll
    for (int mi = 0; mi < 4; mi++) {
        const int r0 = arow0 + warp_m * 64 + mi * 16 + g;
        const int r1 = r0 + 8;
        float lse0 = 0.f, lse1 = 0.f;
#pragma unroll
        for (int ni = 0; ni < 4; ni++) {
            const int cl = warp_n * 32 + ni * 8 + 2 * t;
            const int gc = brow0 + cl;
            const float* c = acc[mi][ni];
            __half2 h01 = __floats2half2_rn(c[0], c[1]);
            __half2 h23 = __floats2half2_rn(c[2], c[3]);
            *reinterpret_cast<__half2*>(&g_S[(size_t)r0 * KP + gc]) = h01;
            *reinterpret_cast<__half2*>(&g_S[(size_t)r1 * KP + gc]) = h23;
            const bool m0 = (gc + 0) < KK;
            const bool m1 = (gc + 1) < KK;
            float e00 = m0 ? __expf(c[0] * INV_EPS) : 0.f;
            float e01 = m1 ? __expf(c[1] * INV_EPS) : 0.f;
            float e10 = m0 ? __expf(c[2] * INV_EPS) : 0.f;
            float e11 = m1 ? __expf(c[3] * INV_EPS) : 0.f;
            colSum[ni][0] += e00 + e10;
            colSum[ni][1] += e01 + e11;
            lse0 += (m0 ? __expf(c[0] * INV_T) : 0.f) + (m1 ? __expf(c[1] * INV_T) : 0.f);
            lse1 += (m0 ? __expf(c[2] * INV_T) : 0.f) + (m1 ? __expf(c[3] * INV_T) : 0.f);
        }
#pragma unroll
        for (int o = 1; o < 4; o <<= 1) {
            lse0 += __shfl_xor_sync(0xffffffffu, lse0, o);
            lse1 += __shfl_xor_sync(0xffffffffu, lse1, o);
        }
        if (t == 0) {
            atomicAdd(&g_lse[r0], lse0);
            atomicAdd(&g_lse[r1], lse1);
        }
    }
#pragma unroll
    for (int ni = 0; ni < 4; ni++) {
#pragma unroll
        for (int o = 4; o < 32; o <<= 1) {
            colSum[ni][0] += __shfl_xor_sync(0xffffffffu, colSum[ni][0], o);
            colSum[ni][1] += __shfl_xor_sync(0xffffffffu, colSum[ni][1], o);
        }
        if (g == 0) {
            const int cl = warp_n * 32 + ni * 8 + 2 * t;
            atomicAdd(&colAcc[cl],     colSum[ni][0]);
            atomicAdd(&colAcc[cl + 1], colSum[ni][1]);
        }
    }
    __syncthreads();
    if (tid < 128) {
        int col = brow0 + tid;
        if (col < KK) atomicAdd(&g_colE[m * KP + col], colAcc[tid]);
    }
}

// ---------------- kernel 3: persistent fused Sinkhorn + loss ----------------
// grid = NCTA (296), 256 threads, 2 CTAs/SM -> all CTAs co-resident.
// Phases separated by monotonic-counter grid barriers.
// Scale-invariance: v = 1/c, u = 1/r (constants cancel in final ratios).

DI void grid_sync(unsigned target) {
    __syncthreads();
    if (threadIdx.x == 0) {
        __threadfence();
        atomicAdd(&g_bar, 1u);
        unsigned v;
        do {
            asm volatile("ld.volatile.global.u32 %0, [%1];" : "=r"(v) : "l"(&g_bar));
        } while (v < target);
    }
    __syncthreads();
}

__global__ __launch_bounds__(256, 2) void k_sink() {
    __shared__ float sv[2 * KP];          // 24 KB: v for both matrices
    __shared__ float sacc[8][256];        // 8 KB: col-phase staging

    const int tid = threadIdx.x;
    const int wid = tid >> 5;
    const int lane = tid & 31;
    const int gwarp = blockIdx.x * 8 + wid;
    const int nwarp = NCTA * 8;           // 2368 warps chip-wide

    // ---- helper lambdas ----
    auto compute_v = [&](const float* src, bool ldcg) {
        for (int idx = tid; idx < 2 * KP; idx += 256) {
            float c = ldcg ? __ldcg(&src[idx]) : src[idx];
            sv[idx] = 1.0f / c;            // pad cols -> inf, never read
        }
        __syncthreads();
    };

    auto row_pass = [&]() {               // u_i = 1 / sum_j E_ij * sv_j
        for (int w = gwarp; w < MT; w += nwarp) {
            const int mm = (w >= BB) ? 1 : 0;
            const uint4* row = reinterpret_cast<const uint4*>(&g_S[(size_t)w * KP]);
            const float* v = &sv[mm * KP];
            float acc = 0.f;
#pragma unroll
            for (int it = 0; it < 12; it++) {
                int jp = lane + it * 32;
                if (jp < 375) {            // 375*8 = 3000 exactly: pad skipped
                    uint4 pk = row[jp];
                    float2 s0 = __half22float2(*reinterpret_cast<__half2*>(&pk.x));
                    float2 s1 = __half22float2(*reinterpret_cast<__half2*>(&pk.y));
                    float2 s2 = __half22float2(*reinterpret_cast<__half2*>(&pk.z));
                    float2 s3 = __half22float2(*reinterpret_cast<__half2*>(&pk.w));
                    const float* vv = &v[jp * 8];
                    acc += __expf(s0.x * INV_EPS) * vv[0] + __expf(s0.y * INV_EPS) * vv[1]
                         + __expf(s1.x * INV_EPS) * vv[2] + __expf(s1.y * INV_EPS) * vv[3]
                         + __expf(s2.x * INV_EPS) * vv[4] + __expf(s2.y * INV_EPS) * vv[5]
                         + __expf(s3.x * INV_EPS) * vv[6] + __expf(s3.y * INV_EPS) * vv[7];
                }
            }
#pragma unroll
            for (int o = 16; o > 0; o >>= 1) acc += __shfl_xor_sync(0xffffffffu, acc, o);
            if (lane == 0) g_u[w] = 1.0f / acc;
        }
    };

    auto col_pass = [&](float* dst) {     // c_j += sum_i E_ij * u_i
        for (int tile = blockIdx.x; tile < 384; tile += NCTA) {
            const int tx = tile % 12;      // col strip of 256
            const int ty = tile / 12;      // row strip of 256
            const int cg = tid & 31;
            const int wr = tid >> 5;
            const int c0 = tx * 256 + cg * 8;
            const int row0 = ty * 256;
            const int mm = (row0 >= BB) ? 1 : 0;
            float acc[8];
#pragma unroll
            for (int e = 0; e < 8; e++) acc[e] = 0.f;
#pragma unroll 4
            for (int r = row0 + wr; r < row0 + 256; r += 8) {
                uint4 pk = *reinterpret_cast<const uint4*>(&g_S[(size_t)r * KP + c0]);
                float u = __ldcg(&g_u[r]);
                float2 f0 = __half22float2(*reinterpret_cast<__half2*>(&pk.x));
                float2 f1 = __half22float2(*reinterpret_cast<__half2*>(&pk.y));
                float2 f2 = __half22float2(*reinterpret_cast<__half2*>(&pk.z));
                float2 f3 = __half22float2(*reinterpret_cast<__half2*>(&pk.w));
                acc[0] += __expf(f0.x * INV_EPS) * u;
                acc[1] += __expf(f0.y * INV_EPS) * u;
                acc[2] += __expf(f1.x * INV_EPS) * u;
                acc[3] += __expf(f1.y * INV_EPS) * u;
                acc[4] += __expf(f2.x * INV_EPS) * u;
                acc[5] += __expf(f2.y * INV_EPS) * u;
                acc[6] += __expf(f3.x * INV_EPS) * u;
                acc[7] += __expf(f3.y * INV_EPS) * u;
            }
#pragma unroll
            for (int e = 0; e < 8; e++) sacc[wr][cg + 32 * e] = acc[e];
            __syncthreads();
            const int c = tid;
            const int col = tx * 256 + c;
            if (col < KK) {
                const int sidx = (c >> 3) + 32 * (c & 7);
                float s = 0.f;
#pragma unroll
                for (int w = 0; w < 8; w++) s += sacc[w][sidx];
                atomicAdd(&dst[(size_t)mm * KP + col], s);
            }
            __syncthreads();
        }
    };

    // ---- phase sequence ----
    compute_v(g_colE, false);              // v0 = 1/colE  (fresh L1: ok)
    row_pass();                            // sinkhorn iter 1 row -> u
    grid_sync(NCTA * 1);

    col_pass(g_cA);                        // iter 2 col -> cA
    grid_sync(NCTA * 2);

    compute_v(g_cA, true);                 // v = 1/cA (ldcg: atomics bypass L1)
    row_pass();                            // iter 2 row -> u
    grid_sync(NCTA * 3);

    col_pass(g_cB);                        // iter 3 col -> cB
    grid_sync(NCTA * 4);

    compute_v(g_cB, true);                 // v = 1/cB
    // ---- loss phase (fused final row pass), warp per batch index i ----
    for (int i = gwarp; i < BB; i += nwarp) {
        const uint4* s1p = reinterpret_cast<const uint4*>(&g_S[(size_t)i * KP]);
        const uint4* s2p = reinterpret_cast<const uint4*>(&g_S[(size_t)(i + BB) * KP]);
        float a1 = 0.f, a2 = 0.f, q1 = 0.f, q2 = 0.f;
#pragma unroll
        for (int it = 0; it < 12; it++) {
            int jp = lane + it * 32;
            if (jp < 375) {
                uint4 p1 = s1p[jp];
                uint4 p2 = s2p[jp];
                const float* v1 = &sv[jp * 8];
                const float* v2 = &sv[KP + jp * 8];
                float s1v[8], s2v[8];
                {
                    float2 f;
                    f = __half22float2(*reinterpret_cast<__half2*>(&p1.x)); s1v[0]=f.x; s1v[1]=f.y;
                    f = __half22float2(*reinterpret_cast<__half2*>(&p1.y)); s1v[2]=f.x; s1v[3]=f.y;
                    f = __half22float2(*reinterpret_cast<__half2*>(&p1.z)); s1v[4]=f.x; s1v[5]=f.y;
                    f = __half22float2(*reinterpret_cast<__half2*>(&p1.w)); s1v[6]=f.x; s1v[7]=f.y;
                    f = __half22float2(*reinterpret_cast<__half2*>(&p2.x)); s2v[0]=f.x; s2v[1]=f.y;
                    f = __half22float2(*reinterpret_cast<__half2*>(&p2.y)); s2v[2]=f.x; s2v[3]=f.y;
                    f = __half22float2(*reinterpret_cast<__half2*>(&p2.z)); s2v[4]=f.x; s2v[5]=f.y;
                    f = __half22float2(*reinterpret_cast<__half2*>(&p2.w)); s2v[6]=f.x; s2v[7]=f.y;
                }
#pragma unroll
                for (int e = 0; e < 8; e++) {
                    float w1 = __expf(s1v[e] * INV_EPS) * v1[e];
                    float w2 = __expf(s2v[e] * INV_EPS) * v2[e];
                    a2 += w2 * s1v[e];
                    a1 += w1 * s2v[e];
                    q1 += w1;
                    q2 += w2;
                }
            }
        }
#pragma unroll
        for (int o = 16; o > 0; o >>= 1) {
            a1 += __shfl_xor_sync(0xffffffffu, a1, o);
            a2 += __shfl_xor_sync(0xffffffffu, a2, o);
            q1 += __shfl_xor_sync(0xffffffffu, q1, o);
            q2 += __shfl_xor_sync(0xffffffffu, q2, o);
        }
        if (lane == 0) {
            float u1 = 1.0f / (4096.0f * q1);      // true u (scale cancels)
            float u2 = 1.0f / (4096.0f * q2);
            float lse1 = logf(g_lse[i]);
            float lse2 = logf(g_lse[i + BB]);
            float contrib = u2 * a2 * INV_T - lse1 * (1.0f / BB)
                          + u1 * a1 * INV_T - lse2 * (1.0f / BB);
            atomicAdd(&g_loss, (double)contrib);
        }
    }
}

// ---------------- finalize ----------------
__global__ void k_final(float* out) {
    out[0] = (float)(-g_loss * (1.0 / (2.0 * BB)));
}

// ---------------- launch ----------------
extern "C" void kernel_launch(void* const* d_in, const int* in_sizes, int n_in,
                              void* d_out, int out_size) {
    (void)in_sizes; (void)n_in; (void)out_size;
    const float* z1 = (const float*)d_in[0];
    const float* z2 = (const float*)d_in[1];
    const float* W  = (const float*)d_in[2];
    float* out = (float*)d_out;

    k_zero<<<32, 256>>>();
    k_conv<<<11264, 256>>>(z1, z2, W);
    k_gemm<<<dim3(24, 64), 256>>>();
    k_sink<<<NCTA, 256>>>();
    k_final<<<1, 1>>>(out);
}

// round 16
// speedup vs baseline: 1.0712x; 1.0712x over previous
#include <cuda_runtime.h>
#include <cuda_bf16.h>
#include <cuda_fp16.h>
#include <cstdint>

#define DI __device__ __forceinline__

// ---------------- problem constants ----------------
namespace {
constexpr int BB = 4096;        // batch
constexpr int DD = 1024;        // feature dim
constexpr int KK = 3000;        // prototypes
constexpr int KP = 3072;        // padded K
constexpr int MT = 8192;        // stacked rows (z1 then z2)
constexpr float INV_EPS = 20.0f;   // 1/0.05
constexpr float INV_T   = 10.0f;   // 1/0.1
}

// ---------------- scratch (device globals; no runtime alloc) ----------------
__device__ __nv_bfloat16 g_Abf[(size_t)MT * DD];   // 16.8 MB
__device__ __nv_bfloat16 g_Wbf[(size_t)KP * DD];   // 6.3 MB (rows >= 3000 zero)
__device__ __half        g_S[(size_t)MT * KP];     // 50.3 MB fp16 scores
__device__ float  g_colE[2 * KP];
__device__ float  g_cA[2 * KP];     // col sums, sinkhorn iter 2
__device__ float  g_cB[2 * KP];     // col sums, sinkhorn iter 3
__device__ float  g_v[2 * KP];      // scale-free v = 1/c
__device__ float  g_lse[MT];
__device__ float  g_u[MT];
__device__ double g_loss;

// ---------------- helpers ----------------
DI uint32_t smem_u32(const void* p) {
    uint32_t a;
    asm("{ .reg .u64 t; cvta.to.shared.u64 t, %1; cvt.u32.u64 %0, t; }" : "=r"(a) : "l"(p));
    return a;
}

DI void cp_async16(uint32_t saddr, const void* gptr) {
    asm volatile("cp.async.cg.shared.global [%0], [%1], 16;"
                 :: "r"(saddr), "l"(gptr) : "memory");
}
#define CP_COMMIT()  asm volatile("cp.async.commit_group;" ::: "memory")
#define CP_WAIT(n)   asm volatile("cp.async.wait_group %0;" :: "n"(n) : "memory")

DI void ldsm4(uint32_t& r0, uint32_t& r1, uint32_t& r2, uint32_t& r3, uint32_t a) {
    asm volatile("ldmatrix.sync.aligned.m8n8.x4.shared.b16 {%0,%1,%2,%3}, [%4];"
                 : "=r"(r0), "=r"(r1), "=r"(r2), "=r"(r3) : "r"(a));
}

DI void mma16816(float* d, const uint32_t* a, const uint32_t* b) {
    asm volatile(
        "mma.sync.aligned.m16n8k16.row.col.f32.bf16.bf16.f32 "
        "{%0,%1,%2,%3}, {%4,%5,%6,%7}, {%8,%9}, {%0,%1,%2,%3};"
        : "+f"(d[0]), "+f"(d[1]), "+f"(d[2]), "+f"(d[3])
        : "r"(a[0]), "r"(a[1]), "r"(a[2]), "r"(a[3]), "r"(b[0]), "r"(b[1]));
}

// conflict-free swizzle for 128B-wide rows: chunk ^= row&7
DI uint32_t sw_off(int row, int ch) {
    return (uint32_t)(row * 128 + ((ch ^ (row & 7)) * 16));
}

// ---------------- kernel 1: conv (A,W) + zero accumulators (merged) ---------
__global__ void k_conv(const float* __restrict__ z1, const float* __restrict__ z2,
                       const float* __restrict__ W) {
    int v = blockIdx.x * blockDim.x + threadIdx.x;     // 0..2883583
    if (v < 2097152) {
        const float* src = (v < 1048576) ? (z1 + 4 * (size_t)v)
                                         : (z2 + 4 * (size_t)(v - 1048576));
        float4 f = *reinterpret_cast<const float4*>(src);
        __nv_bfloat162* dst = reinterpret_cast<__nv_bfloat162*>(&g_Abf[4 * (size_t)v]);
        dst[0] = __floats2bfloat162_rn(f.x, f.y);
        dst[1] = __floats2bfloat162_rn(f.z, f.w);
    } else {
        int w = v - 2097152;                           // 0..786431
        int row = w >> 8;
        __nv_bfloat162 lo, hi;
        if (row < KK) {
            float4 f = *reinterpret_cast<const float4*>(W + 4 * (size_t)w);
            lo = __floats2bfloat162_rn(f.x, f.y);
            hi = __floats2bfloat162_rn(f.z, f.w);
        } else {
            lo = __floats2bfloat162_rn(0.f, 0.f);
            hi = lo;
        }
        __nv_bfloat162* dst = reinterpret_cast<__nv_bfloat162*>(&g_Wbf[4 * (size_t)w]);
        dst[0] = lo;
        dst[1] = hi;
    }
    // zeroing (idx space reused)
    if (v < 2 * KP) { g_colE[v] = 0.f; g_cA[v] = 0.f; g_cB[v] = 0.f; }
    if (v < MT) g_lse[v] = 0.f;
    if (v == 0) g_loss = 0.0;
}

// ---------------- kernel 2: mma.sync GEMM + fused pass-A epilogue ------------
// (proven config: 128x128 tile, Kc=64, 3-stage, 2 CTAs/SM — 141.8us)
static constexpr int NK = 16;
static constexpr int STAGES = 3;
static constexpr int STAGE_BYTES = 32768;

__global__ __launch_bounds__(256, 2) void k_gemm() {
    __shared__ __align__(1024) uint8_t sm[STAGES * STAGE_BYTES];

    const int tid = threadIdx.x;
    const int wid = tid >> 5;
    const int lid = tid & 31;
    const int warp_m = wid >> 2;       // 0..1
    const int warp_n = wid & 3;        // 0..3
    const int ntile = blockIdx.x;
    const int rtile = blockIdx.y;
    const int arow0 = rtile * 128;
    const int brow0 = ntile * 128;

    const uint32_t sbase = smem_u32(sm);

    float acc[4][4][4];
#pragma unroll
    for (int mi = 0; mi < 4; mi++)
#pragma unroll
        for (int ni = 0; ni < 4; ni++)
#pragma unroll
            for (int c = 0; c < 4; c++) acc[mi][ni][c] = 0.f;

    auto issue_loads = [&](int kc, int stage) {
        const uint32_t st = sbase + stage * STAGE_BYTES;
#pragma unroll
        for (int i = 0; i < 4; i++) {
            int idx = tid + i * 256;        // 0..1023
            int row = idx >> 3;             // 0..127
            int ch  = idx & 7;              // 16B chunk in 128B row
            int kb  = kc * 64 + ch * 8;     // element offset in k
            uint32_t so = sw_off(row, ch);
            cp_async16(st + so,         &g_Abf[(size_t)(arow0 + row) * DD + kb]);
            cp_async16(st + 16384 + so, &g_Wbf[(size_t)(brow0 + row) * DD + kb]);
        }
    };

#pragma unroll
    for (int s = 0; s < STAGES - 1; s++) {
        issue_loads(s, s);
        CP_COMMIT();
    }

    const int a_rowoff = lid & 15;
    const int a_chsel  = lid >> 4;
    const int b_noff   = ((lid >> 4) & 1) * 8 + (lid & 7);
    const int b_khalf  = (lid >> 3) & 1;

    int stage = 0;
#pragma unroll 1
    for (int kc = 0; kc < NK; kc++) {
        CP_WAIT(1);
        __syncthreads();
        if (kc + STAGES - 1 < NK) {
            int ns = stage + (STAGES - 1);
            if (ns >= STAGES) ns -= STAGES;
            issue_loads(kc + STAGES - 1, ns);
        }
        CP_COMMIT();

        const uint32_t Ab = sbase + stage * STAGE_BYTES;
        const uint32_t Bb = Ab + 16384;
        stage = (stage + 1 == STAGES) ? 0 : stage + 1;

#pragma unroll
        for (int ks = 0; ks < 4; ks++) {
            uint32_t a[4][4];
            const int chA = ks * 2 + a_chsel;
#pragma unroll
            for (int mi = 0; mi < 4; mi++) {
                int row = warp_m * 64 + mi * 16 + a_rowoff;
                ldsm4(a[mi][0], a[mi][1], a[mi][2], a[mi][3], Ab + sw_off(row, chA));
            }
            uint32_t b[4][2];
            const int chB = ks * 2 + b_khalf;
#pragma unroll
            for (int p = 0; p < 2; p++) {
                int row = warp_n * 32 + p * 16 + b_noff;
                uint32_t r0, r1, r2, r3;
                ldsm4(r0, r1, r2, r3, Bb + sw_off(row, chB));
                b[2 * p][0] = r0; b[2 * p][1] = r1;
                b[2 * p + 1][0] = r2; b[2 * p + 1][1] = r3;
            }
#pragma unroll
            for (int mi = 0; mi < 4; mi++)
#pragma unroll
                for (int ni = 0; ni < 4; ni++)
                    mma16816(acc[mi][ni], a[mi], b[ni]);
        }
    }
    __syncthreads();

    const int g = lid >> 2;
    const int t = lid & 3;
    const int m = (arow0 >= BB) ? 1 : 0;

    float* colAcc = reinterpret_cast<float*>(sm);
    if (tid < 128) colAcc[tid] = 0.f;
    __syncthreads();

    float colSum[4][2];
#pragma unroll
    for (int ni = 0; ni < 4; ni++) { colSum[ni][0] = 0.f; colSum[ni][1] = 0.f; }

#pragma unroll
    for (int mi = 0; mi < 4; mi++) {
        const int r0 = arow0 + warp_m * 64 + mi * 16 + g;
        const int r1 = r0 + 8;
        float lse0 = 0.f, lse1 = 0.f;
#pragma unroll
        for (int ni = 0; ni < 4; ni++) {
            const int cl = warp_n * 32 + ni * 8 + 2 * t;
            const int gc = brow0 + cl;
            const float* c = acc[mi][ni];
            __half2 h01 = __floats2half2_rn(c[0], c[1]);
            __half2 h23 = __floats2half2_rn(c[2], c[3]);
            *reinterpret_cast<__half2*>(&g_S[(size_t)r0 * KP + gc]) = h01;
            *reinterpret_cast<__half2*>(&g_S[(size_t)r1 * KP + gc]) = h23;
            const bool m0 = (gc + 0) < KK;
            const bool m1 = (gc + 1) < KK;
            float e00 = m0 ? __expf(c[0] * INV_EPS) : 0.f;
            float e01 = m1 ? __expf(c[1] * INV_EPS) : 0.f;
            float e10 = m0 ? __expf(c[2] * INV_EPS) : 0.f;
            float e11 = m1 ? __expf(c[3] * INV_EPS) : 0.f;
            colSum[ni][0] += e00 + e10;
            colSum[ni][1] += e01 + e11;
            lse0 += (m0 ? __expf(c[0] * INV_T) : 0.f) + (m1 ? __expf(c[1] * INV_T) : 0.f);
            lse1 += (m0 ? __expf(c[2] * INV_T) : 0.f) + (m1 ? __expf(c[3] * INV_T) : 0.f);
        }
#pragma unroll
        for (int o = 1; o < 4; o <<= 1) {
            lse0 += __shfl_xor_sync(0xffffffffu, lse0, o);
            lse1 += __shfl_xor_sync(0xffffffffu, lse1, o);
        }
        if (t == 0) {
            atomicAdd(&g_lse[r0], lse0);
            atomicAdd(&g_lse[r1], lse1);
        }
    }
#pragma unroll
    for (int ni = 0; ni < 4; ni++) {
#pragma unroll
        for (int o = 4; o < 32; o <<= 1) {
            colSum[ni][0] += __shfl_xor_sync(0xffffffffu, colSum[ni][0], o);
            colSum[ni][1] += __shfl_xor_sync(0xffffffffu, colSum[ni][1], o);
        }
        if (g == 0) {
            const int cl = warp_n * 32 + ni * 8 + 2 * t;
            atomicAdd(&colAcc[cl],     colSum[ni][0]);
            atomicAdd(&colAcc[cl + 1], colSum[ni][1]);
        }
    }
    __syncthreads();
    if (tid < 128) {
        int col = brow0 + tid;
        if (col < KK) atomicAdd(&g_colE[m * KP + col], colAcc[tid]);
    }
}

// ---------------- kernel 3: v = 1/c (scale-free, pad -> 0) ----------------
// SEL resolved in DEVICE code (device globals are not valid host pointers!)
template <int SEL>
__global__ void k_vinit() {
    const float* src = (SEL == 0) ? g_colE : (SEL == 1) ? g_cA : g_cB;
    int idx = blockIdx.x * blockDim.x + threadIdx.x;   // 6144 threads
    if (idx < 2 * KP) {
        int j = idx & (KP - 1);
        g_v[idx] = (j < KK) ? 1.0f / src[idx] : 0.0f;
    }
}

// ---------------- kernel 4: row pass (warp per row, materialized v) ---------
// u_i = 1 / sum_j E_ij v_j   (scale-free)
__global__ __launch_bounds__(256) void k_row() {
    const int w = blockIdx.x * 8 + (threadIdx.x >> 5);   // row 0..8191
    const int lane = threadIdx.x & 31;
    const int mm = (w >= BB) ? 1 : 0;
    const uint4* row = reinterpret_cast<const uint4*>(&g_S[(size_t)w * KP]);
    const float4* v4 = reinterpret_cast<const float4*>(&g_v[mm * KP]);
    float acc = 0.f;
#pragma unroll
    for (int it = 0; it < 12; it++) {
        int jp = lane + it * 32;
        if (jp < 375) {                        // 375*8 = 3000: pad skipped
            uint4 pk = row[jp];
            float4 va = v4[2 * jp], vb = v4[2 * jp + 1];
            float2 s0 = __half22float2(*reinterpret_cast<__half2*>(&pk.x));
            float2 s1 = __half22float2(*reinterpret_cast<__half2*>(&pk.y));
            float2 s2 = __half22float2(*reinterpret_cast<__half2*>(&pk.z));
            float2 s3 = __half22float2(*reinterpret_cast<__half2*>(&pk.w));
            acc += __expf(s0.x * INV_EPS) * va.x + __expf(s0.y * INV_EPS) * va.y
                 + __expf(s1.x * INV_EPS) * va.z + __expf(s1.y * INV_EPS) * va.w
                 + __expf(s2.x * INV_EPS) * vb.x + __expf(s2.y * INV_EPS) * vb.y
                 + __expf(s3.x * INV_EPS) * vb.z + __expf(s3.y * INV_EPS) * vb.w;
        }
    }
#pragma unroll
    for (int o = 16; o > 0; o >>= 1) acc += __shfl_xor_sync(0xffffffffu, acc, o);
    if (lane == 0) g_u[w] = 1.0f / acc;
}

// ---------------- kernel 5: col pass (vectorized, proven shape) -------------
template <int BUF>
__global__ __launch_bounds__(256) void k_colT() {
    __shared__ float sacc[8][256];    // [warp][cg + 32*e]
    float* dst = BUF ? g_cB : g_cA;
    const int cg = threadIdx.x & 31;
    const int wr = threadIdx.x >> 5;
    const int c0 = blockIdx.x * 256 + cg * 8;
    const int row0 = blockIdx.y * 256;
    const int mm = (row0 >= BB) ? 1 : 0;

    float acc[8];
#pragma unroll
    for (int e = 0; e < 8; e++) acc[e] = 0.f;

#pragma unroll 4
    for (int r = row0 + wr; r < row0 + 256; r += 8) {
        uint4 pk = *reinterpret_cast<const uint4*>(&g_S[(size_t)r * KP + c0]);
        float u = g_u[r];
        float2 f0 = __half22float2(*reinterpret_cast<__half2*>(&pk.x));
        float2 f1 = __half22float2(*reinterpret_cast<__half2*>(&pk.y));
        float2 f2 = __half22float2(*reinterpret_cast<__half2*>(&pk.z));
        float2 f3 = __half22float2(*reinterpret_cast<__half2*>(&pk.w));
        acc[0] += __expf(f0.x * INV_EPS) * u;
        acc[1] += __expf(f0.y * INV_EPS) * u;
        acc[2] += __expf(f1.x * INV_EPS) * u;
        acc[3] += __expf(f1.y * INV_EPS) * u;
        acc[4] += __expf(f2.x * INV_EPS) * u;
        acc[5] += __expf(f2.y * INV_EPS) * u;
        acc[6] += __expf(f3.x * INV_EPS) * u;
        acc[7] += __expf(f3.y * INV_EPS) * u;
    }
#pragma unroll
    for (int e = 0; e < 8; e++) sacc[wr][cg + 32 * e] = acc[e];
    __syncthreads();

    const int c = threadIdx.x;
    const int col = blockIdx.x * 256 + c;
    if (col < KK) {
        const int sidx = (c >> 3) + 32 * (c & 7);
        float s = 0.f;
#pragma unroll
        for (int w = 0; w < 8; w++) s += sacc[w][sidx];
        atomicAdd(&dst[mm * KP + col], s);
    }
}

// ---------------- kernel 6: loss (warp per i, materialized v, fused row3) ---
__global__ __launch_bounds__(256) void k_loss() {
    const int i = blockIdx.x * 8 + (threadIdx.x >> 5);   // 0..4095
    const int lane = threadIdx.x & 31;
    const uint4* s1p = reinterpret_cast<const uint4*>(&g_S[(size_t)i * KP]);
    const uint4* s2p = reinterpret_cast<const uint4*>(&g_S[(size_t)(i + BB) * KP]);
    const float4* v1 = reinterpret_cast<const float4*>(&g_v[0]);
    const float4* v2 = reinterpret_cast<const float4*>(&g_v[KP]);
    float a1 = 0.f, a2 = 0.f, q1 = 0.f, q2 = 0.f;
#pragma unroll
    for (int it = 0; it < 12; it++) {
        int jp = lane + it * 32;
        if (jp < 375) {
            uint4 p1 = s1p[jp];
            uint4 p2 = s2p[jp];
            float4 v1a = v1[2 * jp], v1b = v1[2 * jp + 1];
            float4 v2a = v2[2 * jp], v2b = v2[2 * jp + 1];
            float s1v[8], s2v[8];
            {
                float2 f;
                f = __half22float2(*reinterpret_cast<__half2*>(&p1.x)); s1v[0]=f.x; s1v[1]=f.y;
                f = __half22float2(*reinterpret_cast<__half2*>(&p1.y)); s1v[2]=f.x; s1v[3]=f.y;
                f = __half22float2(*reinterpret_cast<__half2*>(&p1.z)); s1v[4]=f.x; s1v[5]=f.y;
                f = __half22float2(*reinterpret_cast<__half2*>(&p1.w)); s1v[6]=f.x; s1v[7]=f.y;
                f = __half22float2(*reinterpret_cast<__half2*>(&p2.x)); s2v[0]=f.x; s2v[1]=f.y;
                f = __half22float2(*reinterpret_cast<__half2*>(&p2.y)); s2v[2]=f.x; s2v[3]=f.y;
                f = __half22float2(*reinterpret_cast<__half2*>(&p2.z)); s2v[4]=f.x; s2v[5]=f.y;
                f = __half22float2(*reinterpret_cast<__half2*>(&p2.w)); s2v[6]=f.x; s2v[7]=f.y;
            }
            float v1arr[8] = {v1a.x, v1a.y, v1a.z, v1a.w, v1b.x, v1b.y, v1b.z, v1b.w};
            float v2arr[8] = {v2a.x, v2a.y, v2a.z, v2a.w, v2b.x, v2b.y, v2b.z, v2b.w};
#pragma unroll
            for (int e = 0; e < 8; e++) {
                float w1 = __expf(s1v[e] * INV_EPS) * v1arr[e];
                float w2 = __expf(s2v[e] * INV_EPS) * v2arr[e];
                a2 += w2 * s1v[e];
                a1 += w1 * s2v[e];
                q1 += w1;
                q2 += w2;
            }
        }
    }
#pragma unroll
    for (int o = 16; o > 0; o >>= 1) {
        a1 += __shfl_xor_sync(0xffffffffu, a1, o);
        a2 += __shfl_xor_sync(0xffffffffu, a2, o);
        q1 += __shfl_xor_sync(0xffffffffu, q1, o);
        q2 += __shfl_xor_sync(0xffffffffu, q2, o);
    }
    if (lane == 0) {
        float u1 = 1.0f / (4096.0f * q1);      // true u (v-scale cancels in u*a)
        float u2 = 1.0f / (4096.0f * q2);
        float lse1 = logf(g_lse[i]);
        float lse2 = logf(g_lse[i + BB]);
        float contrib = u2 * a2 * INV_T - lse1 * (1.0f / BB)
                      + u1 * a1 * INV_T - lse2 * (1.0f / BB);
        atomicAdd(&g_loss, (double)contrib);
    }
}

// ---------------- finalize ----------------
__global__ void k_final(float* out) {
    out[0] = (float)(-g_loss * (1.0 / (2.0 * BB)));
}

// ---------------- launch ----------------
extern "C" void kernel_launch(void* const* d_in, const int* in_sizes, int n_in,
                              void* d_out, int out_size) {
    (void)in_sizes; (void)n_in; (void)out_size;
    const float* z1 = (const float*)d_in[0];
    const float* z2 = (const float*)d_in[1];
    const float* W  = (const float*)d_in[2];
    float* out = (float*)d_out;

    k_conv<<<11264, 256>>>(z1, z2, W);      // conv + zeroing merged
    k_gemm<<<dim3(24, 64), 256>>>();
    // sinkhorn iter 1 (col folded into GEMM epilogue)
    k_vinit<0><<<6, 1024>>>();
    k_row<<<1024, 256>>>();
    // iter 2
    k_colT<0><<<dim3(12, 32), 256>>>();
    k_vinit<1><<<6, 1024>>>();
    k_row<<<1024, 256>>>();
    // iter 3 (row folded into loss)
    k_colT<1><<<dim3(12, 32), 256>>>();
    k_vinit<2><<<6, 1024>>>();
    k_loss<<<512, 256>>>();
    k_final<<<1, 1>>>(out);
}

// round 17
// speedup vs baseline: 1.0724x; 1.0011x over previous
#include <cuda_runtime.h>
#include <cuda_bf16.h>
#include <cuda_fp16.h>
#include <cstdint>

#define DI __device__ __forceinline__

// ---------------- problem constants ----------------
namespace {
constexpr int BB = 4096;        // batch
constexpr int DD = 1024;        // feature dim
constexpr int KK = 3000;        // prototypes
constexpr int KP = 3072;        // padded K
constexpr int MT = 8192;        // stacked rows (z1 then z2)
constexpr float INV_EPS = 20.0f;   // 1/0.05
constexpr float INV_T   = 10.0f;   // 1/0.1
}

// ---------------- scratch (device globals; no runtime alloc) ----------------
__device__ __nv_bfloat16 g_Abf[(size_t)MT * DD];   // 16.8 MB
__device__ __nv_bfloat16 g_Wbf[(size_t)KP * DD];   // 6.3 MB (rows >= 3000 zero)
__device__ __half        g_S[(size_t)MT * KP];     // 50.3 MB fp16 scores
__device__ float  g_colE[2 * KP];
__device__ float  g_cA[2 * KP];     // col sums, sinkhorn iter 2
__device__ float  g_cB[2 * KP];     // col sums, sinkhorn iter 3
__device__ float  g_v[2 * KP];      // scale-free v = 1/c
__device__ float  g_lse[MT];
__device__ float  g_u[MT];
__device__ double g_loss;

// ---------------- helpers ----------------
DI uint32_t smem_u32(const void* p) {
    uint32_t a;
    asm("{ .reg .u64 t; cvta.to.shared.u64 t, %1; cvt.u32.u64 %0, t; }" : "=r"(a) : "l"(p));
    return a;
}

DI void cp_async16(uint32_t saddr, const void* gptr) {
    asm volatile("cp.async.cg.shared.global [%0], [%1], 16;"
                 :: "r"(saddr), "l"(gptr) : "memory");
}
#define CP_COMMIT()  asm volatile("cp.async.commit_group;" ::: "memory")
#define CP_WAIT(n)   asm volatile("cp.async.wait_group %0;" :: "n"(n) : "memory")

DI void ldsm4(uint32_t& r0, uint32_t& r1, uint32_t& r2, uint32_t& r3, uint32_t a) {
    asm volatile("ldmatrix.sync.aligned.m8n8.x4.shared.b16 {%0,%1,%2,%3}, [%4];"
                 : "=r"(r0), "=r"(r1), "=r"(r2), "=r"(r3) : "r"(a));
}

DI void mma16816(float* d, const uint32_t* a, const uint32_t* b) {
    asm volatile(
        "mma.sync.aligned.m16n8k16.row.col.f32.bf16.bf16.f32 "
        "{%0,%1,%2,%3}, {%4,%5,%6,%7}, {%8,%9}, {%0,%1,%2,%3};"
        : "+f"(d[0]), "+f"(d[1]), "+f"(d[2]), "+f"(d[3])
        : "r"(a[0]), "r"(a[1]), "r"(a[2]), "r"(a[3]), "r"(b[0]), "r"(b[1]));
}

// conflict-free swizzle for 128B-wide rows: chunk ^= row&7
DI uint32_t sw_off(int row, int ch) {
    return (uint32_t)(row * 128 + ((ch ^ (row & 7)) * 16));
}

DI void unpack8(const uint4& p, float* s) {
    float2 f;
    f = __half22float2(*reinterpret_cast<const __half2*>(&p.x)); s[0] = f.x; s[1] = f.y;
    f = __half22float2(*reinterpret_cast<const __half2*>(&p.y)); s[2] = f.x; s[3] = f.y;
    f = __half22float2(*reinterpret_cast<const __half2*>(&p.z)); s[4] = f.x; s[5] = f.y;
    f = __half22float2(*reinterpret_cast<const __half2*>(&p.w)); s[6] = f.x; s[7] = f.y;
}

// ---------------- kernel 1: conv (A,W) + zero accumulators (merged) ---------
__global__ void k_conv(const float* __restrict__ z1, const float* __restrict__ z2,
                       const float* __restrict__ W) {
    int v = blockIdx.x * blockDim.x + threadIdx.x;     // 0..2883583
    if (v < 2097152) {
        const float* src = (v < 1048576) ? (z1 + 4 * (size_t)v)
                                         : (z2 + 4 * (size_t)(v - 1048576));
        float4 f = *reinterpret_cast<const float4*>(src);
        __nv_bfloat162* dst = reinterpret_cast<__nv_bfloat162*>(&g_Abf[4 * (size_t)v]);
        dst[0] = __floats2bfloat162_rn(f.x, f.y);
        dst[1] = __floats2bfloat162_rn(f.z, f.w);
    } else {
        int w = v - 2097152;                           // 0..786431
        int row = w >> 8;
        __nv_bfloat162 lo, hi;
        if (row < KK) {
            float4 f = *reinterpret_cast<const float4*>(W + 4 * (size_t)w);
            lo = __floats2bfloat162_rn(f.x, f.y);
            hi = __floats2bfloat162_rn(f.z, f.w);
        } else {
            lo = __floats2bfloat162_rn(0.f, 0.f);
            hi = lo;
        }
        __nv_bfloat162* dst = reinterpret_cast<__nv_bfloat162*>(&g_Wbf[4 * (size_t)w]);
        dst[0] = lo;
        dst[1] = hi;
    }
    // zeroing (idx space reused)
    if (v < 2 * KP) { g_colE[v] = 0.f; g_cA[v] = 0.f; g_cB[v] = 0.f; }
    if (v < MT) g_lse[v] = 0.f;
    if (v == 0) g_loss = 0.0;
}

// ---------------- kernel 2: mma.sync GEMM + fused pass-A epilogue ------------
// (proven config: 128x128 tile, Kc=64, 3-stage, 2 CTAs/SM — 141.8us)
static constexpr int NK = 16;
static constexpr int STAGES = 3;
static constexpr int STAGE_BYTES = 32768;

__global__ __launch_bounds__(256, 2) void k_gemm() {
    __shared__ __align__(1024) uint8_t sm[STAGES * STAGE_BYTES];

    const int tid = threadIdx.x;
    const int wid = tid >> 5;
    const int lid = tid & 31;
    const int warp_m = wid >> 2;       // 0..1
    const int warp_n = wid & 3;        // 0..3
    const int ntile = blockIdx.x;
    const int rtile = blockIdx.y;
    const int arow0 = rtile * 128;
    const int brow0 = ntile * 128;

    const uint32_t sbase = smem_u32(sm);

    float acc[4][4][4];
#pragma unroll
    for (int mi = 0; mi < 4; mi++)
#pragma unroll
        for (int ni = 0; ni < 4; ni++)
#pragma unroll
            for (int c = 0; c < 4; c++) acc[mi][ni][c] = 0.f;

    auto issue_loads = [&](int kc, int stage) {
        const uint32_t st = sbase + stage * STAGE_BYTES;
#pragma unroll
        for (int i = 0; i < 4; i++) {
            int idx = tid + i * 256;        // 0..1023
            int row = idx >> 3;             // 0..127
            int ch  = idx & 7;              // 16B chunk in 128B row
            int kb  = kc * 64 + ch * 8;     // element offset in k
            uint32_t so = sw_off(row, ch);
            cp_async16(st + so,         &g_Abf[(size_t)(arow0 + row) * DD + kb]);
            cp_async16(st + 16384 + so, &g_Wbf[(size_t)(brow0 + row) * DD + kb]);
        }
    };

#pragma unroll
    for (int s = 0; s < STAGES - 1; s++) {
        issue_loads(s, s);
        CP_COMMIT();
    }

    const int a_rowoff = lid & 15;
    const int a_chsel  = lid >> 4;
    const int b_noff   = ((lid >> 4) & 1) * 8 + (lid & 7);
    const int b_khalf  = (lid >> 3) & 1;

    int stage = 0;
#pragma unroll 1
    for (int kc = 0; kc < NK; kc++) {
        CP_WAIT(1);
        __syncthreads();
        if (kc + STAGES - 1 < NK) {
            int ns = stage + (STAGES - 1);
            if (ns >= STAGES) ns -= STAGES;
            issue_loads(kc + STAGES - 1, ns);
        }
        CP_COMMIT();

        const uint32_t Ab = sbase + stage * STAGE_BYTES;
        const uint32_t Bb = Ab + 16384;
        stage = (stage + 1 == STAGES) ? 0 : stage + 1;

#pragma unroll
        for (int ks = 0; ks < 4; ks++) {
            uint32_t a[4][4];
            const int chA = ks * 2 + a_chsel;
#pragma unroll
            for (int mi = 0; mi < 4; mi++) {
                int row = warp_m * 64 + mi * 16 + a_rowoff;
                ldsm4(a[mi][0], a[mi][1], a[mi][2], a[mi][3], Ab + sw_off(row, chA));
            }
            uint32_t b[4][2];
            const int chB = ks * 2 + b_khalf;
#pragma unroll
            for (int p = 0; p < 2; p++) {
                int row = warp_n * 32 + p * 16 + b_noff;
                uint32_t r0, r1, r2, r3;
                ldsm4(r0, r1, r2, r3, Bb + sw_off(row, chB));
                b[2 * p][0] = r0; b[2 * p][1] = r1;
                b[2 * p + 1][0] = r2; b[2 * p + 1][1] = r3;
            }
#pragma unroll
            for (int mi = 0; mi < 4; mi++)
#pragma unroll
                for (int ni = 0; ni < 4; ni++)
                    mma16816(acc[mi][ni], a[mi], b[ni]);
        }
    }
    __syncthreads();

    const int g = lid >> 2;
    const int t = lid & 3;
    const int m = (arow0 >= BB) ? 1 : 0;

    float* colAcc = reinterpret_cast<float*>(sm);
    if (tid < 128) colAcc[tid] = 0.f;
    __syncthreads();

    float colSum[4][2];
#pragma unroll
    for (int ni = 0; ni < 4; ni++) { colSum[ni][0] = 0.f; colSum[ni][1] = 0.f; }

#pragma unroll
    for (int mi = 0; mi < 4; mi++) {
        const int r0 = arow0 + warp_m * 64 + mi * 16 + g;
        const int r1 = r0 + 8;
        float lse0 = 0.f, lse1 = 0.f;
#pragma unroll
        for (int ni = 0; ni < 4; ni++) {
            const int cl = warp_n * 32 + ni * 8 + 2 * t;
            const int gc = brow0 + cl;
            const float* c = acc[mi][ni];
            __half2 h01 = __floats2half2_rn(c[0], c[1]);
            __half2 h23 = __floats2half2_rn(c[2], c[3]);
            *reinterpret_cast<__half2*>(&g_S[(size_t)r0 * KP + gc]) = h01;
            *reinterpret_cast<__half2*>(&g_S[(size_t)r1 * KP + gc]) = h23;
            const bool m0 = (gc + 0) < KK;
            const bool m1 = (gc + 1) < KK;
            float e00 = m0 ? __expf(c[0] * INV_EPS) : 0.f;
            float e01 = m1 ? __expf(c[1] * INV_EPS) : 0.f;
            float e10 = m0 ? __expf(c[2] * INV_EPS) : 0.f;
            float e11 = m1 ? __expf(c[3] * INV_EPS) : 0.f;
            colSum[ni][0] += e00 + e10;
            colSum[ni][1] += e01 + e11;
            lse0 += (m0 ? __expf(c[0] * INV_T) : 0.f) + (m1 ? __expf(c[1] * INV_T) : 0.f);
            lse1 += (m0 ? __expf(c[2] * INV_T) : 0.f) + (m1 ? __expf(c[3] * INV_T) : 0.f);
        }
#pragma unroll
        for (int o = 1; o < 4; o <<= 1) {
            lse0 += __shfl_xor_sync(0xffffffffu, lse0, o);
            lse1 += __shfl_xor_sync(0xffffffffu, lse1, o);
        }
        if (t == 0) {
            atomicAdd(&g_lse[r0], lse0);
            atomicAdd(&g_lse[r1], lse1);
        }
    }
#pragma unroll
    for (int ni = 0; ni < 4; ni++) {
#pragma unroll
        for (int o = 4; o < 32; o <<= 1) {
            colSum[ni][0] += __shfl_xor_sync(0xffffffffu, colSum[ni][0], o);
            colSum[ni][1] += __shfl_xor_sync(0xffffffffu, colSum[ni][1], o);
        }
        if (g == 0) {
            const int cl = warp_n * 32 + ni * 8 + 2 * t;
            atomicAdd(&colAcc[cl],     colSum[ni][0]);
            atomicAdd(&colAcc[cl + 1], colSum[ni][1]);
        }
    }
    __syncthreads();
    if (tid < 128) {
        int col = brow0 + tid;
        if (col < KK) atomicAdd(&g_colE[m * KP + col], colAcc[tid]);
    }
}

// ---------------- kernel 3: v = 1/c (scale-free, pad -> 0) ----------------
template <int SEL>
__global__ void k_vinit() {
    const float* src = (SEL == 0) ? g_colE : (SEL == 1) ? g_cA : g_cB;
    int idx = blockIdx.x * blockDim.x + threadIdx.x;   // 6144 threads
    if (idx < 2 * KP) {
        int j = idx & (KP - 1);
        g_v[idx] = (j < KK) ? 1.0f / src[idx] : 0.0f;
    }
}

// ---------------- kernel 4: row pass — warp per row-PAIR (i, i+BB) ----------
// Single wave (512 blocks), dual independent streams for latency hiding.
__global__ __launch_bounds__(256) void k_row() {
    const int i = blockIdx.x * 8 + (threadIdx.x >> 5);   // 0..4095
    const int lane = threadIdx.x & 31;
    const uint4* r1 = reinterpret_cast<const uint4*>(&g_S[(size_t)i * KP]);
    const uint4* r2 = reinterpret_cast<const uint4*>(&g_S[(size_t)(i + BB) * KP]);
    const float4* v1 = reinterpret_cast<const float4*>(&g_v[0]);
    const float4* v2 = reinterpret_cast<const float4*>(&g_v[KP]);
    float acc1 = 0.f, acc2 = 0.f;
#pragma unroll
    for (int it = 0; it < 12; it++) {
        int jp = lane + it * 32;
        if (jp < 375) {                        // 375*8 = 3000: pad skipped
            uint4 p1 = r1[jp];
            uint4 p2 = r2[jp];
            float4 v1a = v1[2 * jp], v1b = v1[2 * jp + 1];
            float4 v2a = v2[2 * jp], v2b = v2[2 * jp + 1];
            float s1[8], s2[8];
            unpack8(p1, s1);
            unpack8(p2, s2);
            float w1[8] = {v1a.x, v1a.y, v1a.z, v1a.w, v1b.x, v1b.y, v1b.z, v1b.w};
            float w2[8] = {v2a.x, v2a.y, v2a.z, v2a.w, v2b.x, v2b.y, v2b.z, v2b.w};
#pragma unroll
            for (int e = 0; e < 8; e++) {
                acc1 += __expf(s1[e] * INV_EPS) * w1[e];
                acc2 += __expf(s2[e] * INV_EPS) * w2[e];
            }
        }
    }
#pragma unroll
    for (int o = 16; o > 0; o >>= 1) {
        acc1 += __shfl_xor_sync(0xffffffffu, acc1, o);
        acc2 += __shfl_xor_sync(0xffffffffu, acc2, o);
    }
    if (lane == 0) {
        g_u[i]      = 1.0f / acc1;
        g_u[i + BB] = 1.0f / acc2;
    }
}

// ---------------- kernel 5: col pass (vectorized, single-wave) --------------
template <int BUF>
__global__ __launch_bounds__(256) void k_colT() {
    __shared__ float sacc[8][256];    // [warp][cg + 32*e]
    float* dst = BUF ? g_cB : g_cA;
    const int cg = threadIdx.x & 31;
    const int wr = threadIdx.x >> 5;
    const int c0 = blockIdx.x * 256 + cg * 8;
    const int row0 = blockIdx.y * 256;
    const int mm = (row0 >= BB) ? 1 : 0;

    float acc[8];
#pragma unroll
    for (int e = 0; e < 8; e++) acc[e] = 0.f;

#pragma unroll 4
    for (int r = row0 + wr; r < row0 + 256; r += 8) {
        uint4 pk = *reinterpret_cast<const uint4*>(&g_S[(size_t)r * KP + c0]);
        float u = g_u[r];
        float2 f0 = __half22float2(*reinterpret_cast<__half2*>(&pk.x));
        float2 f1 = __half22float2(*reinterpret_cast<__half2*>(&pk.y));
        float2 f2 = __half22float2(*reinterpret_cast<__half2*>(&pk.z));
        float2 f3 = __half22float2(*reinterpret_cast<__half2*>(&pk.w));
        acc[0] += __expf(f0.x * INV_EPS) * u;
        acc[1] += __expf(f0.y * INV_EPS) * u;
        acc[2] += __expf(f1.x * INV_EPS) * u;
        acc[3] += __expf(f1.y * INV_EPS) * u;
        acc[4] += __expf(f2.x * INV_EPS) * u;
        acc[5] += __expf(f2.y * INV_EPS) * u;
        acc[6] += __expf(f3.x * INV_EPS) * u;
        acc[7] += __expf(f3.y * INV_EPS) * u;
    }
#pragma unroll
    for (int e = 0; e < 8; e++) sacc[wr][cg + 32 * e] = acc[e];
    __syncthreads();

    const int c = threadIdx.x;
    const int col = blockIdx.x * 256 + c;
    if (col < KK) {
        const int sidx = (c >> 3) + 32 * (c & 7);
        float s = 0.f;
#pragma unroll
        for (int w = 0; w < 8; w++) s += sacc[w][sidx];
        atomicAdd(&dst[mm * KP + col], s);
    }
}

// ---------------- kernel 6: loss — 256 blocks (single wave), 2 i per warp ---
__global__ __launch_bounds__(256) void k_loss() {
    const int lane = threadIdx.x & 31;
    const int gwarp = blockIdx.x * 8 + (threadIdx.x >> 5);   // 0..2047
    const float4* v1 = reinterpret_cast<const float4*>(&g_v[0]);
    const float4* v2 = reinterpret_cast<const float4*>(&g_v[KP]);

#pragma unroll 1
    for (int i = gwarp; i < BB; i += 2048) {
        const uint4* s1p = reinterpret_cast<const uint4*>(&g_S[(size_t)i * KP]);
        const uint4* s2p = reinterpret_cast<const uint4*>(&g_S[(size_t)(i + BB) * KP]);
        float a1 = 0.f, a2 = 0.f, q1 = 0.f, q2 = 0.f;
#pragma unroll
        for (int it = 0; it < 12; it++) {
            int jp = lane + it * 32;
            if (jp < 375) {
                uint4 p1 = s1p[jp];
                uint4 p2 = s2p[jp];
                float4 v1a = v1[2 * jp], v1b = v1[2 * jp + 1];
                float4 v2a = v2[2 * jp], v2b = v2[2 * jp + 1];
                float s1v[8], s2v[8];
                unpack8(p1, s1v);
                unpack8(p2, s2v);
                float v1arr[8] = {v1a.x, v1a.y, v1a.z, v1a.w, v1b.x, v1b.y, v1b.z, v1b.w};
                float v2arr[8] = {v2a.x, v2a.y, v2a.z, v2a.w, v2b.x, v2b.y, v2b.z, v2b.w};
#pragma unroll
                for (int e = 0; e < 8; e++) {
                    float w1 = __expf(s1v[e] * INV_EPS) * v1arr[e];
                    float w2 = __expf(s2v[e] * INV_EPS) * v2arr[e];
                    a2 += w2 * s1v[e];
                    a1 += w1 * s2v[e];
                    q1 += w1;
                    q2 += w2;
                }
            }
        }
#pragma unroll
        for (int o = 16; o > 0; o >>= 1) {
            a1 += __shfl_xor_sync(0xffffffffu, a1, o);
            a2 += __shfl_xor_sync(0xffffffffu, a2, o);
            q1 += __shfl_xor_sync(0xffffffffu, q1, o);
            q2 += __shfl_xor_sync(0xffffffffu, q2, o);
        }
        if (lane == 0) {
            float u1 = 1.0f / (4096.0f * q1);      // true u (v-scale cancels)
            float u2 = 1.0f / (4096.0f * q2);
            float lse1 = logf(g_lse[i]);
            float lse2 = logf(g_lse[i + BB]);
            float contrib = u2 * a2 * INV_T - lse1 * (1.0f / BB)
                          + u1 * a1 * INV_T - lse2 * (1.0f / BB);
            atomicAdd(&g_loss, (double)contrib);
        }
    }
}

// ---------------- finalize ----------------
__global__ void k_final(float* out) {
    out[0] = (float)(-g_loss * (1.0 / (2.0 * BB)));
}

// ---------------- launch ----------------
extern "C" void kernel_launch(void* const* d_in, const int* in_sizes, int n_in,
                              void* d_out, int out_size) {
    (void)in_sizes; (void)n_in; (void)out_size;
    const float* z1 = (const float*)d_in[0];
    const float* z2 = (const float*)d_in[1];
    const float* W  = (const float*)d_in[2];
    float* out = (float*)d_out;

    k_conv<<<11264, 256>>>(z1, z2, W);      // conv + zeroing merged
    k_gemm<<<dim3(24, 64), 256>>>();
    // sinkhorn iter 1 (col folded into GEMM epilogue)
    k_vinit<0><<<6, 1024>>>();
    k_row<<<512, 256>>>();
    // iter 2
    k_colT<0><<<dim3(12, 32), 256>>>();
    k_vinit<1><<<6, 1024>>>();
    k_row<<<512, 256>>>();
    // iter 3 (row folded into loss)
    k_colT<1><<<dim3(12, 32), 256>>>();
    k_vinit<2><<<6, 1024>>>();
    k_loss<<<256, 256>>>();
    k_final<<<1, 1>>>(out);
}